// round 3
// baseline (speedup 1.0000x reference)
#include <cuda_runtime.h>

// URPE: out[b,h,i,j] = probs[b,h,i,j] * toe[h,i,j]
// toe[h,i,j] = (j>=i) ? w[h, 2048 + (j-i)] : w[h, i-j]
// B=2, H=16, L=2048, weights (16, 4096) f32.
//
// One block per row (b,h,i). Stage the Toeplitz row in smem via a coalesced
// cooperative gather, then stream probs*toe with float4s. probs/out are
// single-touch: use streaming cache hints (__ldcs/__stcs) to keep them from
// thrashing L2 sets against each other.

#define L_DIM 2048

__global__ __launch_bounds__(256, 8)
void urpe_kernel(const float4* __restrict__ probs,
                 const float* __restrict__ w,
                 float4* __restrict__ out)
{
    __shared__ float toe_row[L_DIM];

    const unsigned int row = blockIdx.x;          // ((b*16+h)*2048 + i)
    const int i = (int)(row & 2047u);
    const int h = (int)((row >> 11) & 15u);
    const float* __restrict__ wh = w + h * (2 * L_DIM);

    const int tid = threadIdx.x;

    // Cooperative fill: consecutive tid -> consecutive j -> contiguous weight
    // addresses. Weight table is hot/reused -> default (caching) loads.
    #pragma unroll
    for (int j = tid; j < L_DIM; j += 256) {
        int d = j - i;
        toe_row[j] = __ldg(&wh[d >= 0 ? 2048 + d : -d]);
    }
    __syncthreads();

    const float4* __restrict__ toe4 = (const float4*)toe_row;
    const unsigned long long base = (unsigned long long)row * 512ull;

    #pragma unroll
    for (int k = 0; k < 2; ++k) {
        unsigned int c = tid + k * 256;           // float4 column index [0,512)
        float4 v = __ldcs(&probs[base + c]);      // read-once: evict-first
        float4 t = toe4[c];
        float4 r;
        r.x = v.x * t.x;
        r.y = v.y * t.y;
        r.z = v.z * t.z;
        r.w = v.w * t.w;
        __stcs(&out[base + c], r);                // write-once: streaming store
    }
}

extern "C" void kernel_launch(void* const* d_in, const int* in_sizes, int n_in,
                              void* d_out, int out_size)
{
    const float4* probs = (const float4*)d_in[0];   // (2,16,2048,2048) f32
    const float*  w     = (const float*)d_in[1];    // (16, 4096) f32
    float4* out = (float4*)d_out;

    // 2*16*2048 = 65536 rows, one block each
    urpe_kernel<<<65536, 256>>>(probs, w, out);
}

// round 4
// speedup vs baseline: 1.0589x; 1.0589x over previous
#include <cuda_runtime.h>

// URPE: out[b,h,i,j] = probs[b,h,i,j] * toe[h,i,j]
// toe[h,i,j] = (j>=i) ? w[h, 2048 + (j-i)] : w[h, i-j]
// B=2, H=16, L=2048, weights (16, 4096) f32.
//
// One block per row (b,h,i). Prefetch the row's probs (DRAM) into registers
// FIRST, then stage the Toeplitz row in smem (L2-hit gather) while those DRAM
// loads are in flight, sync, multiply, store. Default cache policy everywhere
// (streaming hints measured 10us slower: L2 needs residency to coalesce
// full-line writebacks on sm_103a).

#define L_DIM 2048

__global__ __launch_bounds__(256, 8)
void urpe_kernel(const float4* __restrict__ probs,
                 const float* __restrict__ w,
                 float4* __restrict__ out)
{
    __shared__ float toe_row[L_DIM];

    const unsigned int row = blockIdx.x;          // ((b*16+h)*2048 + i)
    const int i = (int)(row & 2047u);
    const int h = (int)((row >> 11) & 15u);
    const float* __restrict__ wh = w + h * (2 * L_DIM);

    const int tid = threadIdx.x;
    const unsigned long long base = (unsigned long long)row * 512ull;

    // 1) Kick off the DRAM loads immediately (independent of smem).
    float4 v0 = probs[base + tid];
    float4 v1 = probs[base + tid + 256];

    // 2) Overlap: gather the Toeplitz row from L2 into smem.
    #pragma unroll
    for (int j = tid; j < L_DIM; j += 256) {
        int d = j - i;
        toe_row[j] = __ldg(&wh[d >= 0 ? 2048 + d : -d]);
    }
    __syncthreads();

    const float4* __restrict__ toe4 = (const float4*)toe_row;

    // 3) Multiply + store.
    float4 t0 = toe4[tid];
    float4 t1 = toe4[tid + 256];

    float4 r0, r1;
    r0.x = v0.x * t0.x;  r0.y = v0.y * t0.y;
    r0.z = v0.z * t0.z;  r0.w = v0.w * t0.w;
    r1.x = v1.x * t1.x;  r1.y = v1.y * t1.y;
    r1.z = v1.z * t1.z;  r1.w = v1.w * t1.w;

    out[base + tid]       = r0;
    out[base + tid + 256] = r1;
}

extern "C" void kernel_launch(void* const* d_in, const int* in_sizes, int n_in,
                              void* d_out, int out_size)
{
    const float4* probs = (const float4*)d_in[0];   // (2,16,2048,2048) f32
    const float*  w     = (const float*)d_in[1];    // (16, 4096) f32
    float4* out = (float4*)d_out;

    // 2*16*2048 = 65536 rows, one block each
    urpe_kernel<<<65536, 256>>>(probs, w, out);
}